// round 12
// baseline (speedup 1.0000x reference)
#include <cuda_runtime.h>
#include <cuda_bf16.h>
#include <cstdint>

#define C_DIM 256
#define BD    128
#define CN    128
#define KREAL 784
#define KP    832           // padded K (26 * 32)
#define NTILE 26
#define ALPHA 32.0f
#define NBLK  256

// Split bf16 scratch: [C][128][KP] hi/lo for x and cc (54.5MB each)
#define NU4 3407872
__device__ uint4 g_xh[NU4];
__device__ uint4 g_xl[NU4];
__device__ uint4 g_ch[NU4];
__device__ uint4 g_cl[NU4];
__device__ float g_xn[NTILE * C_DIM * BD];   // |x|^2 per-tile partials (c, bd)
__device__ float g_cn[C_DIM * CN];           // |cc|^2 per (c, cn)
__device__ unsigned g_bar;                   // monotonic device barrier counter

__device__ __forceinline__ uint32_t smem_u32(const void* p) {
    uint32_t a;
    asm("{ .reg .u64 t; cvta.to.shared.u64 t, %1; cvt.u32.u64 %0, t; }" : "=r"(a) : "l"(p));
    return a;
}

// 64-byte-row swizzle (rows are 32 bf16 = 64B)
#define SWZ32(off) ((off) ^ (((off) >> 3) & 0x30))

#define CP16(dst, src) \
    asm volatile("cp.async.cg.shared.global [%0], [%1], 16;" :: "r"(dst), "l"(src))
#define CP_COMMIT() asm volatile("cp.async.commit_group;" ::: "memory")

#define LDSM4(r0, r1, r2, r3, addr) \
    asm volatile("ldmatrix.sync.aligned.m8n8.x4.shared.b16 {%0,%1,%2,%3}, [%4];" \
                 : "=r"(r0), "=r"(r1), "=r"(r2), "=r"(r3) : "r"(addr))

#define MMA16816(d, a, b) \
    asm volatile("mma.sync.aligned.m16n8k16.row.col.f32.bf16.bf16.f32 " \
                 "{%0,%1,%2,%3},{%4,%5,%6,%7},{%8,%9},{%0,%1,%2,%3};" \
                 : "+f"((d)[0]), "+f"((d)[1]), "+f"((d)[2]), "+f"((d)[3]) \
                 : "r"((a)[0]), "r"((a)[1]), "r"((a)[2]), "r"((a)[3]), \
                   "r"((b)[0]), "r"((b)[1]))

// ---------------------------------------------------------------------------
// GEMM K-loop (R9/R11-proven): 3-stage K32 pipeline, warp grid 4m x 2n.
// WITHB=1: stage A+B. WITHB=0: stage A only, B read in place (bbase=OF32_AH).
// ---------------------------------------------------------------------------
#define ST32    32768
#define OF32_AH 0
#define OF32_AL 8192
#define OF32_BH 16384
#define OF32_BL 24576
#define NCHUNK  25

template <int WITHB>
__device__ __forceinline__ void gemm_pass(
    uint32_t sbA, const uint4* __restrict__ Ah, const uint4* __restrict__ Al,
    const uint4* __restrict__ Bh, const uint4* __restrict__ Bl,
    uint32_t bbase, float acc[2][8][4], int t, int lane, int wm, int wn)
{
    #pragma unroll
    for (int i = 0; i < 2; i++)
        #pragma unroll
        for (int j = 0; j < 8; j++)
            #pragma unroll
            for (int e = 0; e < 4; e++) acc[i][j][e] = 0.0f;

    auto issue = [&](int kt, int s) {
        uint32_t base = sbA + (uint32_t)s * ST32;
        #pragma unroll
        for (int j = 0; j < 2; j++) {
            int idx = j * 256 + t;
            int row = idx >> 2, q = idx & 3;
            size_t go = (size_t)row * 104 + (size_t)kt * 4 + q;
            uint32_t so = SWZ32((uint32_t)idx * 16);
            CP16(base + OF32_AH + so, (const void*)(Ah + go));
            CP16(base + OF32_AL + so, (const void*)(Al + go));
            if (WITHB) {
                CP16(base + OF32_BH + so, (const void*)(Bh + go));
                CP16(base + OF32_BL + so, (const void*)(Bl + go));
            }
        }
        CP_COMMIT();
    };

    issue(0, 0);
    issue(1, 1);
    issue(2, 2);

    for (int i = 0; i < NCHUNK; i++) {
        if (i < NCHUNK - 2)       asm volatile("cp.async.wait_group 2;" ::: "memory");
        else if (i == NCHUNK - 2) asm volatile("cp.async.wait_group 1;" ::: "memory");
        else                      asm volatile("cp.async.wait_group 0;" ::: "memory");
        __syncthreads();

        uint32_t base = sbA + (uint32_t)(i % 3) * ST32;
        int nkh = (i == NCHUNK - 1) ? 1 : 2;          // real K ends at 784
        for (int kh = 0; kh < nkh; kh++) {
            uint32_t ah[2][4], al[2][4];
            uint32_t offA = SWZ32((uint32_t)((wm + (lane & 15)) * 64
                                  + kh * 32 + ((lane & 16) ? 16 : 0)));
            LDSM4(ah[0][0], ah[0][1], ah[0][2], ah[0][3], base + OF32_AH + offA);
            LDSM4(ah[1][0], ah[1][1], ah[1][2], ah[1][3], base + OF32_AH + offA + 1024);
            LDSM4(al[0][0], al[0][1], al[0][2], al[0][3], base + OF32_AL + offA);
            LDSM4(al[1][0], al[1][1], al[1][2], al[1][3], base + OF32_AL + offA + 1024);

            #pragma unroll
            for (int nh = 0; nh < 2; nh++) {
                uint32_t bh[4][2], bl[4][2];
                uint32_t offB = SWZ32((uint32_t)((wn + nh * 32 + ((lane & 16) ? 8 : 0)
                                      + (lane & 7)) * 64 + kh * 32 + ((lane & 8) ? 16 : 0)));
                LDSM4(bh[0][0], bh[0][1], bh[1][0], bh[1][1], base + bbase + offB);
                LDSM4(bh[2][0], bh[2][1], bh[3][0], bh[3][1], base + bbase + offB + 1024);
                LDSM4(bl[0][0], bl[0][1], bl[1][0], bl[1][1], base + bbase + 8192 + offB);
                LDSM4(bl[2][0], bl[2][1], bl[3][0], bl[3][1], base + bbase + 8192 + offB + 1024);
                #pragma unroll
                for (int mt = 0; mt < 2; mt++)
                    #pragma unroll
                    for (int nt = 0; nt < 4; nt++) {
                        int np = nh * 4 + nt;
                        MMA16816(acc[mt][np], ah[mt], bh[nt]);
                        MMA16816(acc[mt][np], al[mt], bh[nt]);
                        MMA16816(acc[mt][np], ah[mt], bl[nt]);
                    }
            }
        }
        __syncthreads();
        if (i + 3 < NCHUNK) issue(i + 3, (i + 3) % 3);
    }
}

// ---------------------------------------------------------------------------
// THE kernel: persistent, 256 CTAs, role-split phase1 + device barrier +
// x-dist phase2 with fused softmax.
// ---------------------------------------------------------------------------
__global__ void __launch_bounds__(256, 2)
fused_all(const float* __restrict__ x,   const float* __restrict__ lnw,
          const float* __restrict__ lnb, const float* __restrict__ cc,
          float* __restrict__ out)
{
    extern __shared__ char dsm[];
    uint32_t sb0 = smem_u32(dsm);
    uint32_t sbA = (sb0 + 1023u) & ~1023u;
    char* smA = dsm + (sbA - sb0);
    float* sCn = (float*)(smA + 3 * ST32);
    float* sXn = sCn + 128;

    const size_t OUT1 = (size_t)BD * C_DIM * CN;
    int t = threadIdx.x, lane = t & 31, w = t >> 5;
    int wm = (w & 3) * 32, wn = (w >> 2) * 64;
    int bid = blockIdx.x;

    float acc[2][8][4];
    float* ebuf = (float*)smA;

    // ===================== PHASE 1 =====================
    if (bid & 1) {
        // ---------- cc role: split + cc-dist for c = j and j+128 ----------
        int j = bid >> 1;
        __nv_bfloat16* ch = (__nv_bfloat16*)g_ch;
        __nv_bfloat16* cl = (__nv_bfloat16*)g_cl;

        #pragma unroll 1
        for (int rep = 0; rep < 2; rep++) {
            int c = j + rep * 128;

            // split 128 rows of cc[c]: one warp per row, 16 iterations
            #pragma unroll 1
            for (int it = 0; it < 16; it++) {
                int lr  = it * 8 + w;
                int row = c * CN + lr;
                const float4* src = (const float4*)(cc + (size_t)row * KREAL);
                float ssq = 0.0f;
                #pragma unroll
                for (int i = 0; i < 7; i++) {
                    int k4 = lane + 32 * i;
                    if (k4 < KP / 4) {
                        float4 v = (k4 < KREAL / 4) ? src[k4]
                                                    : make_float4(0.f, 0.f, 0.f, 0.f);
                        ssq += v.x*v.x + v.y*v.y + v.z*v.z + v.w*v.w;
                        ushort4 hs, ls;
                        float e; __nv_bfloat16 h;
                        e = v.x; h = __float2bfloat16(e); hs.x = __bfloat16_as_ushort(h);
                        ls.x = __bfloat16_as_ushort(__float2bfloat16(e - __bfloat162float(h)));
                        e = v.y; h = __float2bfloat16(e); hs.y = __bfloat16_as_ushort(h);
                        ls.y = __bfloat16_as_ushort(__float2bfloat16(e - __bfloat162float(h)));
                        e = v.z; h = __float2bfloat16(e); hs.z = __bfloat16_as_ushort(h);
                        ls.z = __bfloat16_as_ushort(__float2bfloat16(e - __bfloat162float(h)));
                        e = v.w; h = __float2bfloat16(e); hs.w = __bfloat16_as_ushort(h);
                        ls.w = __bfloat16_as_ushort(__float2bfloat16(e - __bfloat162float(h)));
                        size_t o = (size_t)row * KP + (size_t)k4 * 4;
                        *(ushort4*)(ch + o) = hs;
                        *(ushort4*)(cl + o) = ls;
                    }
                }
                #pragma unroll
                for (int o = 16; o > 0; o >>= 1)
                    ssq += __shfl_xor_sync(0xffffffffu, ssq, o);
                if (lane == 0) { g_cn[row] = ssq; sCn[lr] = ssq; }
            }
            __threadfence();
            __syncthreads();

            // cc-dist GEMM for c (A staged from just-written scratch, L2-hot)
            size_t boff = (size_t)c * 13312;
            gemm_pass<0>(sbA, g_ch + boff, g_cl + boff, g_ch + boff, g_cl + boff,
                         OF32_AH, acc, t, lane, wm, wn);

            #pragma unroll
            for (int mt = 0; mt < 2; mt++)
                #pragma unroll
                for (int np = 0; np < 8; np++)
                    #pragma unroll
                    for (int e = 0; e < 4; e++) {
                        int m = wm + mt * 16 + (lane >> 2) + ((e >> 1) << 3);
                        int n = wn + np * 8 + ((lane & 3) << 1) + (e & 1);
                        float d2 = sCn[m] + sCn[n] - 2.0f * acc[mt][np][e];
                        ebuf[n * 132 + m] = sqrtf(fmaxf(d2, 1e-12f));
                    }
            __syncthreads();

            float* o2 = out + 2 * OUT1 + (size_t)c * (CN * CN);
            #pragma unroll
            for (int jj = 0; jj < 16; jj++) {
                int idx = jj * 256 + t;
                int n = idx >> 5, m4 = idx & 31;
                *(float4*)(o2 + (size_t)n * CN + m4 * 4) =
                    *(const float4*)&ebuf[n * 132 + m4 * 4];
            }
            __syncthreads();
        }
    } else {
        // ---------- ln role: LayerNorm+split for bd = bid/2, 26 hw tiles ----------
        int bd = bid >> 1;
        float (*s)[C_DIM + 1] = (float(*)[C_DIM + 1])smA;
        __nv_bfloat16* xh = (__nv_bfloat16*)g_xh;
        __nv_bfloat16* xl = (__nv_bfloat16*)g_xl;

        #pragma unroll 1
        for (int tile = 0; tile < NTILE; tile++) {
            int hw0 = tile * 32;
            #pragma unroll
            for (int i = 0; i < 4; i++) {
                int p  = w * 4 + i;
                int hw = hw0 + p;
                int c0 = lane * 4, c1 = 128 + lane * 4;
                if (hw < KREAL) {
                    const float4* row = (const float4*)(x + ((size_t)bd * KREAL + hw) * C_DIM);
                    float4 v0 = row[lane];
                    float4 v1 = row[lane + 32];
                    float s1 = v0.x + v0.y + v0.z + v0.w + v1.x + v1.y + v1.z + v1.w;
                    float s2 = v0.x*v0.x + v0.y*v0.y + v0.z*v0.z + v0.w*v0.w
                             + v1.x*v1.x + v1.y*v1.y + v1.z*v1.z + v1.w*v1.w;
                    #pragma unroll
                    for (int o = 16; o > 0; o >>= 1) {
                        s1 += __shfl_xor_sync(0xffffffffu, s1, o);
                        s2 += __shfl_xor_sync(0xffffffffu, s2, o);
                    }
                    float mean = s1 * (1.0f / C_DIM);
                    float var  = s2 * (1.0f / C_DIM) - mean * mean;
                    float rs   = rsqrtf(var + 1e-5f);
                    s[p][c0+0] = (v0.x - mean) * rs * lnw[c0+0] + lnb[c0+0];
                    s[p][c0+1] = (v0.y - mean) * rs * lnw[c0+1] + lnb[c0+1];
                    s[p][c0+2] = (v0.z - mean) * rs * lnw[c0+2] + lnb[c0+2];
                    s[p][c0+3] = (v0.w - mean) * rs * lnw[c0+3] + lnb[c0+3];
                    s[p][c1+0] = (v1.x - mean) * rs * lnw[c1+0] + lnb[c1+0];
                    s[p][c1+1] = (v1.y - mean) * rs * lnw[c1+1] + lnb[c1+1];
                    s[p][c1+2] = (v1.z - mean) * rs * lnw[c1+2] + lnb[c1+2];
                    s[p][c1+3] = (v1.w - mean) * rs * lnw[c1+3] + lnb[c1+3];
                } else {
                    #pragma unroll
                    for (int e = 0; e < 4; e++) { s[p][c0+e] = 0.0f; s[p][c1+e] = 0.0f; }
                }
            }
            __syncthreads();

            float nacc[4] = {0.f, 0.f, 0.f, 0.f};
            #pragma unroll
            for (int pass = 0; pass < 4; pass++) {
                int c  = w * 32 + pass * 8 + (lane >> 2);
                int h0 = (lane & 3) * 8;
                unsigned short hs[8], ls[8];
                #pragma unroll
                for (int h = 0; h < 8; h++) {
                    float v = s[h0 + h][c];
                    nacc[pass] = fmaf(v, v, nacc[pass]);
                    __nv_bfloat16 hb = __float2bfloat16(v);
                    hs[h] = __bfloat16_as_ushort(hb);
                    ls[h] = __bfloat16_as_ushort(__float2bfloat16(v - __bfloat162float(hb)));
                }
                size_t idx = (size_t)c * (BD * KP) + (size_t)bd * KP + hw0 + h0;
                *(uint4*)(xh + idx) = *(uint4*)hs;
                *(uint4*)(xl + idx) = *(uint4*)ls;
            }

            #pragma unroll
            for (int pass = 0; pass < 4; pass++) {
                float v = nacc[pass];
                v += __shfl_xor_sync(0xffffffffu, v, 1);
                v += __shfl_xor_sync(0xffffffffu, v, 2);
                if ((lane & 3) == 0) {
                    int c = w * 32 + pass * 8 + (lane >> 2);
                    g_xn[(size_t)tile * (C_DIM * BD) + (size_t)c * BD + bd] = v;
                }
            }
            __syncthreads();
        }
    }

    // ===================== DEVICE BARRIER =====================
    __threadfence();
    __syncthreads();
    if (t == 0) {
        unsigned v = atomicAdd(&g_bar, 1u);
        unsigned target = ((v >> 8) + 1u) << 8;      // this launch's generation
        while (*(volatile unsigned*)&g_bar < target) { }
        __threadfence();
    }
    __syncthreads();

    // ===================== PHASE 2: x-distance + softmax, c = bid ==========
    int c = bid;
    size_t boff = (size_t)c * 13312;

    if (t < 128) sCn[t] = g_cn[(size_t)c * CN + t];
    else {
        int n = t - 128;
        float sv = 0.f;
        #pragma unroll
        for (int p = 0; p < NTILE; p++)
            sv += g_xn[(size_t)p * (C_DIM * BD) + (size_t)c * BD + n];
        sXn[n] = sv;
    }

    gemm_pass<1>(sbA, g_ch + boff, g_cl + boff, g_xh + boff, g_xl + boff,
                 OF32_BH, acc, t, lane, wm, wn);

    #pragma unroll
    for (int mt = 0; mt < 2; mt++)
        #pragma unroll
        for (int np = 0; np < 8; np++)
            #pragma unroll
            for (int e = 0; e < 4; e++) {
                int m = wm + mt * 16 + (lane >> 2) + ((e >> 1) << 3);
                int n = wn + np * 8 + ((lane & 3) << 1) + (e & 1);
                float d2 = sCn[m] + sXn[n] - 2.0f * acc[mt][np][e];
                ebuf[n * 132 + m] = sqrtf(fmaxf(d2, 1e-12f));
            }
    __syncthreads();

    float* aout = out + OUT1;
    #pragma unroll
    for (int rj = 0; rj < 16; rj++) {
        int r = w * 16 + rj;                          // bd row
        float4 v = *(const float4*)&ebuf[r * 132 + lane * 4];
        *(float4*)(out + ((size_t)r * C_DIM + c) * CN + lane * 4) = v;
        float mn = fminf(fminf(v.x, v.y), fminf(v.z, v.w));
        #pragma unroll
        for (int o = 16; o > 0; o >>= 1) mn = fminf(mn, __shfl_xor_sync(0xffffffffu, mn, o));
        float e0 = __expf(-ALPHA * (v.x - mn));
        float e1 = __expf(-ALPHA * (v.y - mn));
        float e2 = __expf(-ALPHA * (v.z - mn));
        float e3 = __expf(-ALPHA * (v.w - mn));
        float sum = e0 + e1 + e2 + e3;
        #pragma unroll
        for (int o = 16; o > 0; o >>= 1) sum += __shfl_xor_sync(0xffffffffu, sum, o);
        float inv = 1.0f / sum;
        *(float4*)(aout + ((size_t)r * C_DIM + c) * CN + lane * 4) =
            make_float4(e0 * inv, e1 * inv, e2 * inv, e3 * inv);
    }
}

// ---------------------------------------------------------------------------
extern "C" void kernel_launch(void* const* d_in, const int* in_sizes, int n_in,
                              void* d_out, int out_size) {
    const float* x   = (const float*)d_in[0];
    const float* lnw = (const float*)d_in[1];
    const float* lnb = (const float*)d_in[2];
    const float* cc  = (const float*)d_in[3];
    float* out = (float*)d_out;

    const int SMEM = 3 * ST32 + 1024 + 1024;        // 100,352 B -> 2 CTAs/SM

    cudaFuncSetAttribute(fused_all, cudaFuncAttributeMaxDynamicSharedMemorySize, SMEM);

    fused_all<<<NBLK, 256, SMEM>>>(x, lnw, lnb, cc, out);
}

// round 13
// speedup vs baseline: 1.0472x; 1.0472x over previous
#include <cuda_runtime.h>
#include <cuda_bf16.h>
#include <cstdint>

#define C_DIM 256
#define BD    128
#define CN    128
#define KREAL 784
#define KP    832           // padded K (26 * 32)
#define NTILE 26
#define ALPHA 32.0f

// Split bf16 scratch: [C][128][KP] hi/lo for x and cc (54.5MB each)
#define NU4 3407872
__device__ uint4 g_xh[NU4];
__device__ uint4 g_xl[NU4];
__device__ uint4 g_ch[NU4];
__device__ uint4 g_cl[NU4];
__device__ float g_xn[NTILE * C_DIM * BD];   // |x|^2 per-tile partials (c, bd)
__device__ float g_cn[C_DIM * CN];           // |cc|^2 per (c, cn)
__device__ int   g_ctr;                      // work queue (reset by prep)

__device__ __forceinline__ uint32_t smem_u32(const void* p) {
    uint32_t a;
    asm("{ .reg .u64 t; cvta.to.shared.u64 t, %1; cvt.u32.u64 %0, t; }" : "=r"(a) : "l"(p));
    return a;
}

// 64-byte-row swizzle (rows are 32 bf16 = 64B)
#define SWZ32(off) ((off) ^ (((off) >> 3) & 0x30))

#define CP16(dst, src) \
    asm volatile("cp.async.cg.shared.global [%0], [%1], 16;" :: "r"(dst), "l"(src))
#define CP_COMMIT() asm volatile("cp.async.commit_group;" ::: "memory")

#define LDSM4(r0, r1, r2, r3, addr) \
    asm volatile("ldmatrix.sync.aligned.m8n8.x4.shared.b16 {%0,%1,%2,%3}, [%4];" \
                 : "=r"(r0), "=r"(r1), "=r"(r2), "=r"(r3) : "r"(addr))

#define MMA16816(d, a, b) \
    asm volatile("mma.sync.aligned.m16n8k16.row.col.f32.bf16.bf16.f32 " \
                 "{%0,%1,%2,%3},{%4,%5,%6,%7},{%8,%9},{%0,%1,%2,%3};" \
                 : "+f"((d)[0]), "+f"((d)[1]), "+f"((d)[2]), "+f"((d)[3]) \
                 : "r"((a)[0]), "r"((a)[1]), "r"((a)[2]), "r"((a)[3]), \
                   "r"((b)[0]), "r"((b)[1]))

// ---------------------------------------------------------------------------
// Fused prep kernel (R11-proven): interleaved heterogeneous grid, 7424 blocks.
//   even ids < 6656  -> ln tile   (sub = id>>1, 3328 tiles)
//   odd  ids / tail  -> cc rows   (8 rows per block, 4096 blocks)
// Also resets the GEMM work-queue counter (stream-ordered before GEMM).
// ---------------------------------------------------------------------------
__global__ void prep_kernel(const float* __restrict__ x,
                            const float* __restrict__ lnw,
                            const float* __restrict__ lnb,
                            const float* __restrict__ cc) {
    __shared__ float s[32][C_DIM + 1];
    int id = blockIdx.x;
    if (id == 0 && threadIdx.x == 0) g_ctr = 0;
    int type, sub;
    if (id < 6656) { type = id & 1; sub = id >> 1; }
    else           { type = 1;      sub = id - 6656 + 3328; }

    int lane = threadIdx.x & 31;
    int warp = threadIdx.x >> 5;

    if (type == 1) {
        // ================= cc split: 8 rows, one warp per row =============
        int row = sub * 8 + warp;
        const float4* src = (const float4*)(cc + (size_t)row * KREAL);
        __nv_bfloat16* ch = (__nv_bfloat16*)g_ch;
        __nv_bfloat16* cl = (__nv_bfloat16*)g_cl;
        float ssq = 0.0f;
        #pragma unroll
        for (int i = 0; i < 7; i++) {
            int k4 = lane + 32 * i;
            if (k4 < KP / 4) {
                float4 v = (k4 < KREAL / 4) ? src[k4] : make_float4(0.f, 0.f, 0.f, 0.f);
                ssq += v.x*v.x + v.y*v.y + v.z*v.z + v.w*v.w;
                ushort4 hs, ls;
                float e; __nv_bfloat16 h;
                e = v.x; h = __float2bfloat16(e); hs.x = __bfloat16_as_ushort(h);
                ls.x = __bfloat16_as_ushort(__float2bfloat16(e - __bfloat162float(h)));
                e = v.y; h = __float2bfloat16(e); hs.y = __bfloat16_as_ushort(h);
                ls.y = __bfloat16_as_ushort(__float2bfloat16(e - __bfloat162float(h)));
                e = v.z; h = __float2bfloat16(e); hs.z = __bfloat16_as_ushort(h);
                ls.z = __bfloat16_as_ushort(__float2bfloat16(e - __bfloat162float(h)));
                e = v.w; h = __float2bfloat16(e); hs.w = __bfloat16_as_ushort(h);
                ls.w = __bfloat16_as_ushort(__float2bfloat16(e - __bfloat162float(h)));
                size_t o = (size_t)row * KP + (size_t)k4 * 4;
                *(ushort4*)(ch + o) = hs;
                *(ushort4*)(cl + o) = ls;
            }
        }
        #pragma unroll
        for (int o = 16; o > 0; o >>= 1) ssq += __shfl_xor_sync(0xffffffffu, ssq, o);
        if (lane == 0) g_cn[row] = ssq;
        return;
    }

    // ================= LayerNorm tile (R7-proven path) ====================
    int bd   = sub & 127;
    int tile = sub >> 7;
    int hw0  = tile * 32;

    #pragma unroll
    for (int i = 0; i < 4; i++) {
        int p  = warp * 4 + i;
        int hw = hw0 + p;
        int c0 = lane * 4, c1 = 128 + lane * 4;
        if (hw < KREAL) {
            const float4* row = (const float4*)(x + ((size_t)bd * KREAL + hw) * C_DIM);
            float4 v0 = row[lane];
            float4 v1 = row[lane + 32];
            float s1 = v0.x + v0.y + v0.z + v0.w + v1.x + v1.y + v1.z + v1.w;
            float s2 = v0.x*v0.x + v0.y*v0.y + v0.z*v0.z + v0.w*v0.w
                     + v1.x*v1.x + v1.y*v1.y + v1.z*v1.z + v1.w*v1.w;
            #pragma unroll
            for (int o = 16; o > 0; o >>= 1) {
                s1 += __shfl_xor_sync(0xffffffffu, s1, o);
                s2 += __shfl_xor_sync(0xffffffffu, s2, o);
            }
            float mean = s1 * (1.0f / C_DIM);
            float var  = s2 * (1.0f / C_DIM) - mean * mean;
            float rs   = rsqrtf(var + 1e-5f);
            s[p][c0+0] = (v0.x - mean) * rs * lnw[c0+0] + lnb[c0+0];
            s[p][c0+1] = (v0.y - mean) * rs * lnw[c0+1] + lnb[c0+1];
            s[p][c0+2] = (v0.z - mean) * rs * lnw[c0+2] + lnb[c0+2];
            s[p][c0+3] = (v0.w - mean) * rs * lnw[c0+3] + lnb[c0+3];
            s[p][c1+0] = (v1.x - mean) * rs * lnw[c1+0] + lnb[c1+0];
            s[p][c1+1] = (v1.y - mean) * rs * lnw[c1+1] + lnb[c1+1];
            s[p][c1+2] = (v1.z - mean) * rs * lnw[c1+2] + lnb[c1+2];
            s[p][c1+3] = (v1.w - mean) * rs * lnw[c1+3] + lnb[c1+3];
        } else {
            #pragma unroll
            for (int e = 0; e < 4; e++) { s[p][c0+e] = 0.0f; s[p][c1+e] = 0.0f; }
        }
    }
    __syncthreads();

    __nv_bfloat16* xh = (__nv_bfloat16*)g_xh;
    __nv_bfloat16* xl = (__nv_bfloat16*)g_xl;
    float nacc[4] = {0.f, 0.f, 0.f, 0.f};

    #pragma unroll
    for (int pass = 0; pass < 4; pass++) {
        int c  = warp * 32 + pass * 8 + (lane >> 2);
        int h0 = (lane & 3) * 8;
        unsigned short hs[8], ls[8];
        #pragma unroll
        for (int h = 0; h < 8; h++) {
            float v = s[h0 + h][c];
            nacc[pass] = fmaf(v, v, nacc[pass]);
            __nv_bfloat16 hb = __float2bfloat16(v);
            hs[h] = __bfloat16_as_ushort(hb);
            ls[h] = __bfloat16_as_ushort(__float2bfloat16(v - __bfloat162float(hb)));
        }
        size_t idx = (size_t)c * (BD * KP) + (size_t)bd * KP + hw0 + h0;
        *(uint4*)(xh + idx) = *(uint4*)hs;
        *(uint4*)(xl + idx) = *(uint4*)ls;
    }

    #pragma unroll
    for (int pass = 0; pass < 4; pass++) {
        float v = nacc[pass];
        v += __shfl_xor_sync(0xffffffffu, v, 1);
        v += __shfl_xor_sync(0xffffffffu, v, 2);
        if ((lane & 3) == 0) {
            int c = warp * 32 + pass * 8 + (lane >> 2);
            g_xn[(size_t)tile * (C_DIM * BD) + (size_t)c * BD + bd] = v;
        }
    }
}

// ---------------------------------------------------------------------------
// GEMM K-loop (R9/R11-proven): 3-stage K32 pipeline, warp grid 4m x 2n.
// WITHB=1: stage A+B. WITHB=0: stage A only, B read in place (bbase=OF32_AH).
// ---------------------------------------------------------------------------
#define ST32    32768
#define OF32_AH 0
#define OF32_AL 8192
#define OF32_BH 16384
#define OF32_BL 24576
#define NCHUNK  25

template <int WITHB>
__device__ __forceinline__ void gemm_pass(
    uint32_t sbA, const uint4* __restrict__ Ah, const uint4* __restrict__ Al,
    const uint4* __restrict__ Bh, const uint4* __restrict__ Bl,
    uint32_t bbase, float acc[2][8][4], int t, int lane, int wm, int wn)
{
    #pragma unroll
    for (int i = 0; i < 2; i++)
        #pragma unroll
        for (int j = 0; j < 8; j++)
            #pragma unroll
            for (int e = 0; e < 4; e++) acc[i][j][e] = 0.0f;

    auto issue = [&](int kt, int s) {
        uint32_t base = sbA + (uint32_t)s * ST32;
        #pragma unroll
        for (int j = 0; j < 2; j++) {
            int idx = j * 256 + t;
            int row = idx >> 2, q = idx & 3;
            size_t go = (size_t)row * 104 + (size_t)kt * 4 + q;
            uint32_t so = SWZ32((uint32_t)idx * 16);
            CP16(base + OF32_AH + so, (const void*)(Ah + go));
            CP16(base + OF32_AL + so, (const void*)(Al + go));
            if (WITHB) {
                CP16(base + OF32_BH + so, (const void*)(Bh + go));
                CP16(base + OF32_BL + so, (const void*)(Bl + go));
            }
        }
        CP_COMMIT();
    };

    issue(0, 0);
    issue(1, 1);
    issue(2, 2);

    for (int i = 0; i < NCHUNK; i++) {
        if (i < NCHUNK - 2)       asm volatile("cp.async.wait_group 2;" ::: "memory");
        else if (i == NCHUNK - 2) asm volatile("cp.async.wait_group 1;" ::: "memory");
        else                      asm volatile("cp.async.wait_group 0;" ::: "memory");
        __syncthreads();

        uint32_t base = sbA + (uint32_t)(i % 3) * ST32;
        int nkh = (i == NCHUNK - 1) ? 1 : 2;          // real K ends at 784
        for (int kh = 0; kh < nkh; kh++) {
            uint32_t ah[2][4], al[2][4];
            uint32_t offA = SWZ32((uint32_t)((wm + (lane & 15)) * 64
                                  + kh * 32 + ((lane & 16) ? 16 : 0)));
            LDSM4(ah[0][0], ah[0][1], ah[0][2], ah[0][3], base + OF32_AH + offA);
            LDSM4(ah[1][0], ah[1][1], ah[1][2], ah[1][3], base + OF32_AH + offA + 1024);
            LDSM4(al[0][0], al[0][1], al[0][2], al[0][3], base + OF32_AL + offA);
            LDSM4(al[1][0], al[1][1], al[1][2], al[1][3], base + OF32_AL + offA + 1024);

            #pragma unroll
            for (int nh = 0; nh < 2; nh++) {
                uint32_t bh[4][2], bl[4][2];
                uint32_t offB = SWZ32((uint32_t)((wn + nh * 32 + ((lane & 16) ? 8 : 0)
                                      + (lane & 7)) * 64 + kh * 32 + ((lane & 8) ? 16 : 0)));
                LDSM4(bh[0][0], bh[0][1], bh[1][0], bh[1][1], base + bbase + offB);
                LDSM4(bh[2][0], bh[2][1], bh[3][0], bh[3][1], base + bbase + offB + 1024);
                LDSM4(bl[0][0], bl[0][1], bl[1][0], bl[1][1], base + bbase + 8192 + offB);
                LDSM4(bl[2][0], bl[2][1], bl[3][0], bl[3][1], base + bbase + 8192 + offB + 1024);
                #pragma unroll
                for (int mt = 0; mt < 2; mt++)
                    #pragma unroll
                    for (int nt = 0; nt < 4; nt++) {
                        int np = nh * 4 + nt;
                        MMA16816(acc[mt][np], ah[mt], bh[nt]);
                        MMA16816(acc[mt][np], al[mt], bh[nt]);
                        MMA16816(acc[mt][np], ah[mt], bl[nt]);
                    }
            }
        }
        __syncthreads();
        if (i + 3 < NCHUNK) issue(i + 3, (i + 3) % 3);
    }
}

// ---------------------------------------------------------------------------
// Persistent GEMM: 256 CTAs, atomic queue of 512 half-items.
//   item = (c = ws>>1, pass = ws&1): pass 0 = x-dist + fused softmax,
//   pass 1 = cc-dist. Work-conserving across the 108x2 + 40x1 CTA placement.
// ---------------------------------------------------------------------------
__global__ void __launch_bounds__(256, 2)
dist_gemm_all(float* __restrict__ out) {
    extern __shared__ char dsm[];
    __shared__ int s_ws;
    uint32_t sb0 = smem_u32(dsm);
    uint32_t sbA = (sb0 + 1023u) & ~1023u;
    char* smA = dsm + (sbA - sb0);
    float* sCn = (float*)(smA + 3 * ST32);
    float* sXn = sCn + 128;

    const size_t OUT1 = (size_t)BD * C_DIM * CN;
    int t = threadIdx.x, lane = t & 31, w = t >> 5;
    int wm = (w & 3) * 32, wn = (w >> 2) * 64;

    float acc[2][8][4];
    float* ebuf = (float*)smA;

    while (true) {
        if (t == 0) s_ws = atomicAdd(&g_ctr, 1);
        __syncthreads();                              // broadcast + smem reuse guard
        int ws = s_ws;
        if (ws >= 2 * C_DIM) break;
        int c = ws >> 1;
        int xpass = !(ws & 1);

        size_t boff = (size_t)c * 13312;              // 128 rows * 104 uint4

        if (t < 128) sCn[t] = g_cn[(size_t)c * CN + t];
        else if (xpass) {
            int n = t - 128;
            float sv = 0.f;
            #pragma unroll
            for (int p = 0; p < NTILE; p++)
                sv += g_xn[(size_t)p * (C_DIM * BD) + (size_t)c * BD + n];
            sXn[n] = sv;
        }

        if (xpass) {
            // ---------------- x-distance + fused softmax ----------------
            gemm_pass<1>(sbA, g_ch + boff, g_cl + boff, g_xh + boff, g_xl + boff,
                         OF32_BH, acc, t, lane, wm, wn);

            #pragma unroll
            for (int mt = 0; mt < 2; mt++)
                #pragma unroll
                for (int np = 0; np < 8; np++)
                    #pragma unroll
                    for (int e = 0; e < 4; e++) {
                        int m = wm + mt * 16 + (lane >> 2) + ((e >> 1) << 3);
                        int n = wn + np * 8 + ((lane & 3) << 1) + (e & 1);
                        float d2 = sCn[m] + sXn[n] - 2.0f * acc[mt][np][e];
                        ebuf[n * 132 + m] = sqrtf(fmaxf(d2, 1e-12f));
                    }
            __syncthreads();

            float* aout = out + OUT1;
            #pragma unroll
            for (int rj = 0; rj < 16; rj++) {
                int r = w * 16 + rj;                  // bd row
                float4 v = *(const float4*)&ebuf[r * 132 + lane * 4];
                *(float4*)(out + ((size_t)r * C_DIM + c) * CN + lane * 4) = v;
                float mn = fminf(fminf(v.x, v.y), fminf(v.z, v.w));
                #pragma unroll
                for (int o = 16; o > 0; o >>= 1)
                    mn = fminf(mn, __shfl_xor_sync(0xffffffffu, mn, o));
                float e0 = __expf(-ALPHA * (v.x - mn));
                float e1 = __expf(-ALPHA * (v.y - mn));
                float e2 = __expf(-ALPHA * (v.z - mn));
                float e3 = __expf(-ALPHA * (v.w - mn));
                float sum = e0 + e1 + e2 + e3;
                #pragma unroll
                for (int o = 16; o > 0; o >>= 1)
                    sum += __shfl_xor_sync(0xffffffffu, sum, o);
                float inv = 1.0f / sum;
                *(float4*)(aout + ((size_t)r * C_DIM + c) * CN + lane * 4) =
                    make_float4(e0 * inv, e1 * inv, e2 * inv, e3 * inv);
            }
            __syncthreads();
        } else {
            // ---------------- cc-distance ----------------
            gemm_pass<0>(sbA, g_ch + boff, g_cl + boff, g_ch + boff, g_cl + boff,
                         OF32_AH, acc, t, lane, wm, wn);

            #pragma unroll
            for (int mt = 0; mt < 2; mt++)
                #pragma unroll
                for (int np = 0; np < 8; np++)
                    #pragma unroll
                    for (int e = 0; e < 4; e++) {
                        int m = wm + mt * 16 + (lane >> 2) + ((e >> 1) << 3);
                        int n = wn + np * 8 + ((lane & 3) << 1) + (e & 1);
                        float d2 = sCn[m] + sCn[n] - 2.0f * acc[mt][np][e];
                        ebuf[n * 132 + m] = sqrtf(fmaxf(d2, 1e-12f));
                    }
            __syncthreads();

            float* o2 = out + 2 * OUT1 + (size_t)c * (CN * CN);
            #pragma unroll
            for (int j = 0; j < 16; j++) {
                int idx = j * 256 + t;
                int n = idx >> 5, m4 = idx & 31;
                *(float4*)(o2 + (size_t)n * CN + m4 * 4) =
                    *(const float4*)&ebuf[n * 132 + m4 * 4];
            }
            __syncthreads();
        }
    }
}

// ---------------------------------------------------------------------------
extern "C" void kernel_launch(void* const* d_in, const int* in_sizes, int n_in,
                              void* d_out, int out_size) {
    const float* x   = (const float*)d_in[0];
    const float* lnw = (const float*)d_in[1];
    const float* lnb = (const float*)d_in[2];
    const float* cc  = (const float*)d_in[3];
    float* out = (float*)d_out;

    const int SMEM = 3 * ST32 + 1024 + 1024;        // 100,352 B -> 2 CTAs/SM

    cudaFuncSetAttribute(dist_gemm_all, cudaFuncAttributeMaxDynamicSharedMemorySize, SMEM);

    prep_kernel<<<7424, 256>>>(x, lnw, lnb, cc);    // fused ln + cc split (+ctr reset)
    dist_gemm_all<<<C_DIM, 256, SMEM>>>(out);
}

// round 14
// speedup vs baseline: 1.1713x; 1.1186x over previous
#include <cuda_runtime.h>
#include <cuda_bf16.h>
#include <cstdint>

#define C_DIM 256
#define BD    128
#define CN    128
#define KREAL 784
#define KP    832           // padded K (26 * 32)
#define NTILE 26
#define ALPHA 32.0f

// Split bf16 scratch: [C][128][KP] hi/lo for x and cc (54.5MB each)
#define NU4 3407872
__device__ uint4 g_xh[NU4];
__device__ uint4 g_xl[NU4];
__device__ uint4 g_ch[NU4];
__device__ uint4 g_cl[NU4];
__device__ float g_xn[NTILE * C_DIM * BD];   // |x|^2 per-tile partials (c, bd)
__device__ float g_cn[C_DIM * CN];           // |cc|^2 per (c, cn)

__device__ __forceinline__ uint32_t smem_u32(const void* p) {
    uint32_t a;
    asm("{ .reg .u64 t; cvta.to.shared.u64 t, %1; cvt.u32.u64 %0, t; }" : "=r"(a) : "l"(p));
    return a;
}

// 64-byte-row swizzle (rows are 32 bf16 = 64B)
#define SWZ32(off) ((off) ^ (((off) >> 3) & 0x30))

#define CP16(dst, src) \
    asm volatile("cp.async.cg.shared.global [%0], [%1], 16;" :: "r"(dst), "l"(src))
#define CP_COMMIT() asm volatile("cp.async.commit_group;" ::: "memory")

#define LDSM4(r0, r1, r2, r3, addr) \
    asm volatile("ldmatrix.sync.aligned.m8n8.x4.shared.b16 {%0,%1,%2,%3}, [%4];" \
                 : "=r"(r0), "=r"(r1), "=r"(r2), "=r"(r3) : "r"(addr))

#define MMA16816(d, a, b) \
    asm volatile("mma.sync.aligned.m16n8k16.row.col.f32.bf16.bf16.f32 " \
                 "{%0,%1,%2,%3},{%4,%5,%6,%7},{%8,%9},{%0,%1,%2,%3};" \
                 : "+f"((d)[0]), "+f"((d)[1]), "+f"((d)[2]), "+f"((d)[3]) \
                 : "r"((a)[0]), "r"((a)[1]), "r"((a)[2]), "r"((a)[3]), \
                   "r"((b)[0]), "r"((b)[1]))

// ---------------------------------------------------------------------------
// Fused prep kernel (R11-proven): interleaved heterogeneous grid, 7424 blocks.
//   even ids < 6656  -> ln tile   (sub = id>>1, 3328 tiles)
//   odd  ids / tail  -> cc rows   (8 rows per block, 4096 blocks)
// ---------------------------------------------------------------------------
__global__ void prep_kernel(const float* __restrict__ x,
                            const float* __restrict__ lnw,
                            const float* __restrict__ lnb,
                            const float* __restrict__ cc) {
    __shared__ float s[32][C_DIM + 1];
    int id = blockIdx.x;
    int type, sub;
    if (id < 6656) { type = id & 1; sub = id >> 1; }
    else           { type = 1;      sub = id - 6656 + 3328; }

    int lane = threadIdx.x & 31;
    int warp = threadIdx.x >> 5;

    if (type == 1) {
        // ================= cc split: 8 rows, one warp per row =============
        int row = sub * 8 + warp;
        const float4* src = (const float4*)(cc + (size_t)row * KREAL);
        __nv_bfloat16* ch = (__nv_bfloat16*)g_ch;
        __nv_bfloat16* cl = (__nv_bfloat16*)g_cl;
        float ssq = 0.0f;
        #pragma unroll
        for (int i = 0; i < 7; i++) {
            int k4 = lane + 32 * i;
            if (k4 < KP / 4) {
                float4 v = (k4 < KREAL / 4) ? src[k4] : make_float4(0.f, 0.f, 0.f, 0.f);
                ssq += v.x*v.x + v.y*v.y + v.z*v.z + v.w*v.w;
                ushort4 hs, ls;
                float e; __nv_bfloat16 h;
                e = v.x; h = __float2bfloat16(e); hs.x = __bfloat16_as_ushort(h);
                ls.x = __bfloat16_as_ushort(__float2bfloat16(e - __bfloat162float(h)));
                e = v.y; h = __float2bfloat16(e); hs.y = __bfloat16_as_ushort(h);
                ls.y = __bfloat16_as_ushort(__float2bfloat16(e - __bfloat162float(h)));
                e = v.z; h = __float2bfloat16(e); hs.z = __bfloat16_as_ushort(h);
                ls.z = __bfloat16_as_ushort(__float2bfloat16(e - __bfloat162float(h)));
                e = v.w; h = __float2bfloat16(e); hs.w = __bfloat16_as_ushort(h);
                ls.w = __bfloat16_as_ushort(__float2bfloat16(e - __bfloat162float(h)));
                size_t o = (size_t)row * KP + (size_t)k4 * 4;
                *(ushort4*)(ch + o) = hs;
                *(ushort4*)(cl + o) = ls;
            }
        }
        #pragma unroll
        for (int o = 16; o > 0; o >>= 1) ssq += __shfl_xor_sync(0xffffffffu, ssq, o);
        if (lane == 0) g_cn[row] = ssq;
        return;
    }

    // ================= LayerNorm tile (R7-proven path) ====================
    int bd   = sub & 127;
    int tile = sub >> 7;
    int hw0  = tile * 32;

    #pragma unroll
    for (int i = 0; i < 4; i++) {
        int p  = warp * 4 + i;
        int hw = hw0 + p;
        int c0 = lane * 4, c1 = 128 + lane * 4;
        if (hw < KREAL) {
            const float4* row = (const float4*)(x + ((size_t)bd * KREAL + hw) * C_DIM);
            float4 v0 = row[lane];
            float4 v1 = row[lane + 32];
            float s1 = v0.x + v0.y + v0.z + v0.w + v1.x + v1.y + v1.z + v1.w;
            float s2 = v0.x*v0.x + v0.y*v0.y + v0.z*v0.z + v0.w*v0.w
                     + v1.x*v1.x + v1.y*v1.y + v1.z*v1.z + v1.w*v1.w;
            #pragma unroll
            for (int o = 16; o > 0; o >>= 1) {
                s1 += __shfl_xor_sync(0xffffffffu, s1, o);
                s2 += __shfl_xor_sync(0xffffffffu, s2, o);
            }
            float mean = s1 * (1.0f / C_DIM);
            float var  = s2 * (1.0f / C_DIM) - mean * mean;
            float rs   = rsqrtf(var + 1e-5f);
            s[p][c0+0] = (v0.x - mean) * rs * lnw[c0+0] + lnb[c0+0];
            s[p][c0+1] = (v0.y - mean) * rs * lnw[c0+1] + lnb[c0+1];
            s[p][c0+2] = (v0.z - mean) * rs * lnw[c0+2] + lnb[c0+2];
            s[p][c0+3] = (v0.w - mean) * rs * lnw[c0+3] + lnb[c0+3];
            s[p][c1+0] = (v1.x - mean) * rs * lnw[c1+0] + lnb[c1+0];
            s[p][c1+1] = (v1.y - mean) * rs * lnw[c1+1] + lnb[c1+1];
            s[p][c1+2] = (v1.z - mean) * rs * lnw[c1+2] + lnb[c1+2];
            s[p][c1+3] = (v1.w - mean) * rs * lnw[c1+3] + lnb[c1+3];
        } else {
            #pragma unroll
            for (int e = 0; e < 4; e++) { s[p][c0+e] = 0.0f; s[p][c1+e] = 0.0f; }
        }
    }
    __syncthreads();

    __nv_bfloat16* xh = (__nv_bfloat16*)g_xh;
    __nv_bfloat16* xl = (__nv_bfloat16*)g_xl;
    float nacc[4] = {0.f, 0.f, 0.f, 0.f};

    #pragma unroll
    for (int pass = 0; pass < 4; pass++) {
        int c  = warp * 32 + pass * 8 + (lane >> 2);
        int h0 = (lane & 3) * 8;
        unsigned short hs[8], ls[8];
        #pragma unroll
        for (int h = 0; h < 8; h++) {
            float v = s[h0 + h][c];
            nacc[pass] = fmaf(v, v, nacc[pass]);
            __nv_bfloat16 hb = __float2bfloat16(v);
            hs[h] = __bfloat16_as_ushort(hb);
            ls[h] = __bfloat16_as_ushort(__float2bfloat16(v - __bfloat162float(hb)));
        }
        size_t idx = (size_t)c * (BD * KP) + (size_t)bd * KP + hw0 + h0;
        *(uint4*)(xh + idx) = *(uint4*)hs;
        *(uint4*)(xl + idx) = *(uint4*)ls;
    }

    #pragma unroll
    for (int pass = 0; pass < 4; pass++) {
        float v = nacc[pass];
        v += __shfl_xor_sync(0xffffffffu, v, 1);
        v += __shfl_xor_sync(0xffffffffu, v, 2);
        if ((lane & 3) == 0) {
            int c = warp * 32 + pass * 8 + (lane >> 2);
            g_xn[(size_t)tile * (C_DIM * BD) + (size_t)c * BD + bd] = v;
        }
    }
}

// ---------------------------------------------------------------------------
// GEMM K-loop (R9/R11-proven): 3-stage K32 pipeline, warp grid 4m x 2n.
// WITHB=1: stage A+B. WITHB=0: stage A only, B read in place (bbase=OF32_AH).
// ---------------------------------------------------------------------------
#define ST32    32768
#define OF32_AH 0
#define OF32_AL 8192
#define OF32_BH 16384
#define OF32_BL 24576
#define NCHUNK  25

template <int WITHB>
__device__ __forceinline__ void gemm_pass(
    uint32_t sbA, const uint4* __restrict__ Ah, const uint4* __restrict__ Al,
    const uint4* __restrict__ Bh, const uint4* __restrict__ Bl,
    uint32_t bbase, float acc[2][8][4], int t, int lane, int wm, int wn)
{
    #pragma unroll
    for (int i = 0; i < 2; i++)
        #pragma unroll
        for (int j = 0; j < 8; j++)
            #pragma unroll
            for (int e = 0; e < 4; e++) acc[i][j][e] = 0.0f;

    auto issue = [&](int kt, int s) {
        uint32_t base = sbA + (uint32_t)s * ST32;
        #pragma unroll
        for (int j = 0; j < 2; j++) {
            int idx = j * 256 + t;
            int row = idx >> 2, q = idx & 3;
            size_t go = (size_t)row * 104 + (size_t)kt * 4 + q;
            uint32_t so = SWZ32((uint32_t)idx * 16);
            CP16(base + OF32_AH + so, (const void*)(Ah + go));
            CP16(base + OF32_AL + so, (const void*)(Al + go));
            if (WITHB) {
                CP16(base + OF32_BH + so, (const void*)(Bh + go));
                CP16(base + OF32_BL + so, (const void*)(Bl + go));
            }
        }
        CP_COMMIT();
    };

    issue(0, 0);
    issue(1, 1);
    issue(2, 2);

    for (int i = 0; i < NCHUNK; i++) {
        if (i < NCHUNK - 2)       asm volatile("cp.async.wait_group 2;" ::: "memory");
        else if (i == NCHUNK - 2) asm volatile("cp.async.wait_group 1;" ::: "memory");
        else                      asm volatile("cp.async.wait_group 0;" ::: "memory");
        __syncthreads();

        uint32_t base = sbA + (uint32_t)(i % 3) * ST32;
        int nkh = (i == NCHUNK - 1) ? 1 : 2;          // real K ends at 784
        for (int kh = 0; kh < nkh; kh++) {
            uint32_t ah[2][4], al[2][4];
            uint32_t offA = SWZ32((uint32_t)((wm + (lane & 15)) * 64
                                  + kh * 32 + ((lane & 16) ? 16 : 0)));
            LDSM4(ah[0][0], ah[0][1], ah[0][2], ah[0][3], base + OF32_AH + offA);
            LDSM4(ah[1][0], ah[1][1], ah[1][2], ah[1][3], base + OF32_AH + offA + 1024);
            LDSM4(al[0][0], al[0][1], al[0][2], al[0][3], base + OF32_AL + offA);
            LDSM4(al[1][0], al[1][1], al[1][2], al[1][3], base + OF32_AL + offA + 1024);

            #pragma unroll
            for (int nh = 0; nh < 2; nh++) {
                uint32_t bh[4][2], bl[4][2];
                uint32_t offB = SWZ32((uint32_t)((wn + nh * 32 + ((lane & 16) ? 8 : 0)
                                      + (lane & 7)) * 64 + kh * 32 + ((lane & 8) ? 16 : 0)));
                LDSM4(bh[0][0], bh[0][1], bh[1][0], bh[1][1], base + bbase + offB);
                LDSM4(bh[2][0], bh[2][1], bh[3][0], bh[3][1], base + bbase + offB + 1024);
                LDSM4(bl[0][0], bl[0][1], bl[1][0], bl[1][1], base + bbase + 8192 + offB);
                LDSM4(bl[2][0], bl[2][1], bl[3][0], bl[3][1], base + bbase + 8192 + offB + 1024);
                #pragma unroll
                for (int mt = 0; mt < 2; mt++)
                    #pragma unroll
                    for (int nt = 0; nt < 4; nt++) {
                        int np = nh * 4 + nt;
                        MMA16816(acc[mt][np], ah[mt], bh[nt]);
                        MMA16816(acc[mt][np], al[mt], bh[nt]);
                        MMA16816(acc[mt][np], ah[mt], bl[nt]);
                    }
            }
        }
        __syncthreads();
        if (i + 3 < NCHUNK) issue(i + 3, (i + 3) % 3);
    }
}

// ---------------------------------------------------------------------------
// GEMM: 512 CTAs, one half-item each (HW work-conserving dispatch).
//   even bid: x-dist + fused softmax for c = bid>>1
//   odd  bid: cc-dist for c = bid>>1   (adjacent -> cc[c] shared in L2)
// ---------------------------------------------------------------------------
__global__ void __launch_bounds__(256, 2)
dist_gemm_all(float* __restrict__ out) {
    extern __shared__ char dsm[];
    uint32_t sb0 = smem_u32(dsm);
    uint32_t sbA = (sb0 + 1023u) & ~1023u;
    char* smA = dsm + (sbA - sb0);
    float* sCn = (float*)(smA + 3 * ST32);
    float* sXn = sCn + 128;

    const size_t OUT1 = (size_t)BD * C_DIM * CN;
    int t = threadIdx.x, lane = t & 31, w = t >> 5;
    int wm = (w & 3) * 32, wn = (w >> 2) * 64;

    int bid = blockIdx.x;
    int c = bid >> 1;
    int xpass = !(bid & 1);
    size_t boff = (size_t)c * 13312;                  // 128 rows * 104 uint4

    float acc[2][8][4];
    float* ebuf = (float*)smA;

    if (t < 128) sCn[t] = g_cn[(size_t)c * CN + t];
    else if (xpass) {
        int n = t - 128;
        float sv = 0.f;
        #pragma unroll
        for (int p = 0; p < NTILE; p++)
            sv += g_xn[(size_t)p * (C_DIM * BD) + (size_t)c * BD + n];
        sXn[n] = sv;
    }

    if (xpass) {
        // ---------------- x-distance + fused softmax ----------------
        gemm_pass<1>(sbA, g_ch + boff, g_cl + boff, g_xh + boff, g_xl + boff,
                     OF32_BH, acc, t, lane, wm, wn);

        #pragma unroll
        for (int mt = 0; mt < 2; mt++)
            #pragma unroll
            for (int np = 0; np < 8; np++)
                #pragma unroll
                for (int e = 0; e < 4; e++) {
                    int m = wm + mt * 16 + (lane >> 2) + ((e >> 1) << 3);
                    int n = wn + np * 8 + ((lane & 3) << 1) + (e & 1);
                    float d2 = sCn[m] + sXn[n] - 2.0f * acc[mt][np][e];
                    ebuf[n * 132 + m] = sqrtf(fmaxf(d2, 1e-12f));
                }
        __syncthreads();

        float* aout = out + OUT1;
        #pragma unroll
        for (int rj = 0; rj < 16; rj++) {
            int r = w * 16 + rj;                      // bd row
            float4 v = *(const float4*)&ebuf[r * 132 + lane * 4];
            *(float4*)(out + ((size_t)r * C_DIM + c) * CN + lane * 4) = v;
            float mn = fminf(fminf(v.x, v.y), fminf(v.z, v.w));
            #pragma unroll
            for (int o = 16; o > 0; o >>= 1)
                mn = fminf(mn, __shfl_xor_sync(0xffffffffu, mn, o));
            float e0 = __expf(-ALPHA * (v.x - mn));
            float e1 = __expf(-ALPHA * (v.y - mn));
            float e2 = __expf(-ALPHA * (v.z - mn));
            float e3 = __expf(-ALPHA * (v.w - mn));
            float sum = e0 + e1 + e2 + e3;
            #pragma unroll
            for (int o = 16; o > 0; o >>= 1)
                sum += __shfl_xor_sync(0xffffffffu, sum, o);
            float inv = 1.0f / sum;
            *(float4*)(aout + ((size_t)r * C_DIM + c) * CN + lane * 4) =
                make_float4(e0 * inv, e1 * inv, e2 * inv, e3 * inv);
        }
    } else {
        // ---------------- cc-distance ----------------
        gemm_pass<0>(sbA, g_ch + boff, g_cl + boff, g_ch + boff, g_cl + boff,
                     OF32_AH, acc, t, lane, wm, wn);

        #pragma unroll
        for (int mt = 0; mt < 2; mt++)
            #pragma unroll
            for (int np = 0; np < 8; np++)
                #pragma unroll
                for (int e = 0; e < 4; e++) {
                    int m = wm + mt * 16 + (lane >> 2) + ((e >> 1) << 3);
                    int n = wn + np * 8 + ((lane & 3) << 1) + (e & 1);
                    float d2 = sCn[m] + sCn[n] - 2.0f * acc[mt][np][e];
                    ebuf[n * 132 + m] = sqrtf(fmaxf(d2, 1e-12f));
                }
        __syncthreads();

        float* o2 = out + 2 * OUT1 + (size_t)c * (CN * CN);
        #pragma unroll
        for (int j = 0; j < 16; j++) {
            int idx = j * 256 + t;
            int n = idx >> 5, m4 = idx & 31;
            *(float4*)(o2 + (size_t)n * CN + m4 * 4) =
                *(const float4*)&ebuf[n * 132 + m4 * 4];
        }
    }
}

// ---------------------------------------------------------------------------
extern "C" void kernel_launch(void* const* d_in, const int* in_sizes, int n_in,
                              void* d_out, int out_size) {
    const float* x   = (const float*)d_in[0];
    const float* lnw = (const float*)d_in[1];
    const float* lnb = (const float*)d_in[2];
    const float* cc  = (const float*)d_in[3];
    float* out = (float*)d_out;

    const int SMEM = 3 * ST32 + 1024 + 1024;        // 100,352 B -> 2 CTAs/SM

    cudaFuncSetAttribute(dist_gemm_all, cudaFuncAttributeMaxDynamicSharedMemorySize, SMEM);

    prep_kernel<<<7424, 256>>>(x, lnw, lnb, cc);    // fused ln + cc split
    dist_gemm_all<<<2 * C_DIM, 256, SMEM>>>(out);
}

// round 15
// speedup vs baseline: 1.1844x; 1.0111x over previous
#include <cuda_runtime.h>
#include <cuda_bf16.h>
#include <cstdint>

#define C_DIM 256
#define BD    128
#define CN    128
#define KREAL 784
#define KP    832           // padded K (26 * 32)
#define NTILE 26
#define ALPHA 32.0f

// Split bf16 scratch: [C][128][KP] hi/lo for x and cc (54.5MB each)
#define NU4 3407872
__device__ uint4 g_xh[NU4];
__device__ uint4 g_xl[NU4];
__device__ uint4 g_ch[NU4];
__device__ uint4 g_cl[NU4];
__device__ float g_xn[NTILE * C_DIM * BD];   // |x|^2 per-tile partials (c, bd)
__device__ float g_cn[C_DIM * CN];           // |cc|^2 per (c, cn)

__device__ __forceinline__ uint32_t smem_u32(const void* p) {
    uint32_t a;
    asm("{ .reg .u64 t; cvta.to.shared.u64 t, %1; cvt.u32.u64 %0, t; }" : "=r"(a) : "l"(p));
    return a;
}

// 64-byte-row swizzle (rows are 32 bf16 = 64B)
#define SWZ32(off) ((off) ^ (((off) >> 3) & 0x30))

#define CP16(dst, src) \
    asm volatile("cp.async.cg.shared.global [%0], [%1], 16;" :: "r"(dst), "l"(src))
#define CP_COMMIT() asm volatile("cp.async.commit_group;" ::: "memory")

#define LDSM4(r0, r1, r2, r3, addr) \
    asm volatile("ldmatrix.sync.aligned.m8n8.x4.shared.b16 {%0,%1,%2,%3}, [%4];" \
                 : "=r"(r0), "=r"(r1), "=r"(r2), "=r"(r3) : "r"(addr))

// NOTE: non-volatile — pure register op; lets ptxas schedule around LDSM and
// break accumulator dependency chains.
#define MMA16816(d, a, b) \
    asm("mma.sync.aligned.m16n8k16.row.col.f32.bf16.bf16.f32 " \
        "{%0,%1,%2,%3},{%4,%5,%6,%7},{%8,%9},{%0,%1,%2,%3};" \
        : "+f"((d)[0]), "+f"((d)[1]), "+f"((d)[2]), "+f"((d)[3]) \
        : "r"((a)[0]), "r"((a)[1]), "r"((a)[2]), "r"((a)[3]), \
          "r"((b)[0]), "r"((b)[1]))

// ---------------------------------------------------------------------------
// Fused prep kernel (R11-proven): interleaved heterogeneous grid, 7424 blocks.
//   even ids < 6656  -> ln tile   (sub = id>>1, 3328 tiles)
//   odd  ids / tail  -> cc rows   (8 rows per block, 4096 blocks)
// ---------------------------------------------------------------------------
__global__ void prep_kernel(const float* __restrict__ x,
                            const float* __restrict__ lnw,
                            const float* __restrict__ lnb,
                            const float* __restrict__ cc) {
    __shared__ float s[32][C_DIM + 1];
    int id = blockIdx.x;
    int type, sub;
    if (id < 6656) { type = id & 1; sub = id >> 1; }
    else           { type = 1;      sub = id - 6656 + 3328; }

    int lane = threadIdx.x & 31;
    int warp = threadIdx.x >> 5;

    if (type == 1) {
        // ================= cc split: 8 rows, one warp per row =============
        int row = sub * 8 + warp;
        const float4* src = (const float4*)(cc + (size_t)row * KREAL);
        __nv_bfloat16* ch = (__nv_bfloat16*)g_ch;
        __nv_bfloat16* cl = (__nv_bfloat16*)g_cl;
        float ssq = 0.0f;
        #pragma unroll
        for (int i = 0; i < 7; i++) {
            int k4 = lane + 32 * i;
            if (k4 < KP / 4) {
                float4 v = (k4 < KREAL / 4) ? src[k4] : make_float4(0.f, 0.f, 0.f, 0.f);
                ssq += v.x*v.x + v.y*v.y + v.z*v.z + v.w*v.w;
                ushort4 hs, ls;
                float e; __nv_bfloat16 h;
                e = v.x; h = __float2bfloat16(e); hs.x = __bfloat16_as_ushort(h);
                ls.x = __bfloat16_as_ushort(__float2bfloat16(e - __bfloat162float(h)));
                e = v.y; h = __float2bfloat16(e); hs.y = __bfloat16_as_ushort(h);
                ls.y = __bfloat16_as_ushort(__float2bfloat16(e - __bfloat162float(h)));
                e = v.z; h = __float2bfloat16(e); hs.z = __bfloat16_as_ushort(h);
                ls.z = __bfloat16_as_ushort(__float2bfloat16(e - __bfloat162float(h)));
                e = v.w; h = __float2bfloat16(e); hs.w = __bfloat16_as_ushort(h);
                ls.w = __bfloat16_as_ushort(__float2bfloat16(e - __bfloat162float(h)));
                size_t o = (size_t)row * KP + (size_t)k4 * 4;
                *(ushort4*)(ch + o) = hs;
                *(ushort4*)(cl + o) = ls;
            }
        }
        #pragma unroll
        for (int o = 16; o > 0; o >>= 1) ssq += __shfl_xor_sync(0xffffffffu, ssq, o);
        if (lane == 0) g_cn[row] = ssq;
        return;
    }

    // ================= LayerNorm tile (R7-proven path) ====================
    int bd   = sub & 127;
    int tile = sub >> 7;
    int hw0  = tile * 32;

    #pragma unroll
    for (int i = 0; i < 4; i++) {
        int p  = warp * 4 + i;
        int hw = hw0 + p;
        int c0 = lane * 4, c1 = 128 + lane * 4;
        if (hw < KREAL) {
            const float4* row = (const float4*)(x + ((size_t)bd * KREAL + hw) * C_DIM);
            float4 v0 = row[lane];
            float4 v1 = row[lane + 32];
            float s1 = v0.x + v0.y + v0.z + v0.w + v1.x + v1.y + v1.z + v1.w;
            float s2 = v0.x*v0.x + v0.y*v0.y + v0.z*v0.z + v0.w*v0.w
                     + v1.x*v1.x + v1.y*v1.y + v1.z*v1.z + v1.w*v1.w;
            #pragma unroll
            for (int o = 16; o > 0; o >>= 1) {
                s1 += __shfl_xor_sync(0xffffffffu, s1, o);
                s2 += __shfl_xor_sync(0xffffffffu, s2, o);
            }
            float mean = s1 * (1.0f / C_DIM);
            float var  = s2 * (1.0f / C_DIM) - mean * mean;
            float rs   = rsqrtf(var + 1e-5f);
            s[p][c0+0] = (v0.x - mean) * rs * lnw[c0+0] + lnb[c0+0];
            s[p][c0+1] = (v0.y - mean) * rs * lnw[c0+1] + lnb[c0+1];
            s[p][c0+2] = (v0.z - mean) * rs * lnw[c0+2] + lnb[c0+2];
            s[p][c0+3] = (v0.w - mean) * rs * lnw[c0+3] + lnb[c0+3];
            s[p][c1+0] = (v1.x - mean) * rs * lnw[c1+0] + lnb[c1+0];
            s[p][c1+1] = (v1.y - mean) * rs * lnw[c1+1] + lnb[c1+1];
            s[p][c1+2] = (v1.z - mean) * rs * lnw[c1+2] + lnb[c1+2];
            s[p][c1+3] = (v1.w - mean) * rs * lnw[c1+3] + lnb[c1+3];
        } else {
            #pragma unroll
            for (int e = 0; e < 4; e++) { s[p][c0+e] = 0.0f; s[p][c1+e] = 0.0f; }
        }
    }
    __syncthreads();

    __nv_bfloat16* xh = (__nv_bfloat16*)g_xh;
    __nv_bfloat16* xl = (__nv_bfloat16*)g_xl;
    float nacc[4] = {0.f, 0.f, 0.f, 0.f};

    #pragma unroll
    for (int pass = 0; pass < 4; pass++) {
        int c  = warp * 32 + pass * 8 + (lane >> 2);
        int h0 = (lane & 3) * 8;
        unsigned short hs[8], ls[8];
        #pragma unroll
        for (int h = 0; h < 8; h++) {
            float v = s[h0 + h][c];
            nacc[pass] = fmaf(v, v, nacc[pass]);
            __nv_bfloat16 hb = __float2bfloat16(v);
            hs[h] = __bfloat16_as_ushort(hb);
            ls[h] = __bfloat16_as_ushort(__float2bfloat16(v - __bfloat162float(hb)));
        }
        size_t idx = (size_t)c * (BD * KP) + (size_t)bd * KP + hw0 + h0;
        *(uint4*)(xh + idx) = *(uint4*)hs;
        *(uint4*)(xl + idx) = *(uint4*)ls;
    }

    #pragma unroll
    for (int pass = 0; pass < 4; pass++) {
        float v = nacc[pass];
        v += __shfl_xor_sync(0xffffffffu, v, 1);
        v += __shfl_xor_sync(0xffffffffu, v, 2);
        if ((lane & 3) == 0) {
            int c = warp * 32 + pass * 8 + (lane >> 2);
            g_xn[(size_t)tile * (C_DIM * BD) + (size_t)c * BD + bd] = v;
        }
    }
}

// ---------------------------------------------------------------------------
// GEMM K-loop: 3-stage K32 pipeline, warp grid 4m x 2n.
// TERM-MAJOR MMA ordering: per nh-half, 8 independent MMAs per split term
// (reuse distance 8 per accumulator -> hides HMMA accumulate latency).
// ---------------------------------------------------------------------------
#define ST32    32768
#define OF32_AH 0
#define OF32_AL 8192
#define OF32_BH 16384
#define OF32_BL 24576
#define NCHUNK  25

template <int WITHB>
__device__ __forceinline__ void gemm_pass(
    uint32_t sbA, const uint4* __restrict__ Ah, const uint4* __restrict__ Al,
    const uint4* __restrict__ Bh, const uint4* __restrict__ Bl,
    uint32_t bbase, float acc[2][8][4], int t, int lane, int wm, int wn)
{
    #pragma unroll
    for (int i = 0; i < 2; i++)
        #pragma unroll
        for (int j = 0; j < 8; j++)
            #pragma unroll
            for (int e = 0; e < 4; e++) acc[i][j][e] = 0.0f;

    auto issue = [&](int kt, int s) {
        uint32_t base = sbA + (uint32_t)s * ST32;
        #pragma unroll
        for (int j = 0; j < 2; j++) {
            int idx = j * 256 + t;
            int row = idx >> 2, q = idx & 3;
            size_t go = (size_t)row * 104 + (size_t)kt * 4 + q;
            uint32_t so = SWZ32((uint32_t)idx * 16);
            CP16(base + OF32_AH + so, (const void*)(Ah + go));
            CP16(base + OF32_AL + so, (const void*)(Al + go));
            if (WITHB) {
                CP16(base + OF32_BH + so, (const void*)(Bh + go));
                CP16(base + OF32_BL + so, (const void*)(Bl + go));
            }
        }
        CP_COMMIT();
    };

    issue(0, 0);
    issue(1, 1);
    issue(2, 2);

    for (int i = 0; i < NCHUNK; i++) {
        if (i < NCHUNK - 2)       asm volatile("cp.async.wait_group 2;" ::: "memory");
        else if (i == NCHUNK - 2) asm volatile("cp.async.wait_group 1;" ::: "memory");
        else                      asm volatile("cp.async.wait_group 0;" ::: "memory");
        __syncthreads();

        uint32_t base = sbA + (uint32_t)(i % 3) * ST32;
        int nkh = (i == NCHUNK - 1) ? 1 : 2;          // real K ends at 784
        for (int kh = 0; kh < nkh; kh++) {
            uint32_t ah[2][4], al[2][4];
            uint32_t offA = SWZ32((uint32_t)((wm + (lane & 15)) * 64
                                  + kh * 32 + ((lane & 16) ? 16 : 0)));
            LDSM4(ah[0][0], ah[0][1], ah[0][2], ah[0][3], base + OF32_AH + offA);
            LDSM4(ah[1][0], ah[1][1], ah[1][2], ah[1][3], base + OF32_AH + offA + 1024);
            LDSM4(al[0][0], al[0][1], al[0][2], al[0][3], base + OF32_AL + offA);
            LDSM4(al[1][0], al[1][1], al[1][2], al[1][3], base + OF32_AL + offA + 1024);

            #pragma unroll
            for (int nh = 0; nh < 2; nh++) {
                uint32_t bh[4][2], bl[4][2];
                uint32_t offB = SWZ32((uint32_t)((wn + nh * 32 + ((lane & 16) ? 8 : 0)
                                      + (lane & 7)) * 64 + kh * 32 + ((lane & 8) ? 16 : 0)));
                LDSM4(bh[0][0], bh[0][1], bh[1][0], bh[1][1], base + bbase + offB);
                LDSM4(bh[2][0], bh[2][1], bh[3][0], bh[3][1], base + bbase + offB + 1024);
                LDSM4(bl[0][0], bl[0][1], bl[1][0], bl[1][1], base + bbase + 8192 + offB);
                LDSM4(bl[2][0], bl[2][1], bl[3][0], bl[3][1], base + bbase + 8192 + offB + 1024);

                // term-major: 8 independent MMAs per term; per-acc term order
                // unchanged (hh -> lh -> hl) so numerics are identical.
                #pragma unroll
                for (int mt = 0; mt < 2; mt++)
                    #pragma unroll
                    for (int nt = 0; nt < 4; nt++)
                        MMA16816(acc[mt][nh * 4 + nt], ah[mt], bh[nt]);
                #pragma unroll
                for (int mt = 0; mt < 2; mt++)
                    #pragma unroll
                    for (int nt = 0; nt < 4; nt++)
                        MMA16816(acc[mt][nh * 4 + nt], al[mt], bh[nt]);
                #pragma unroll
                for (int mt = 0; mt < 2; mt++)
                    #pragma unroll
                    for (int nt = 0; nt < 4; nt++)
                        MMA16816(acc[mt][nh * 4 + nt], ah[mt], bl[nt]);
            }
        }
        __syncthreads();
        if (i + 3 < NCHUNK) issue(i + 3, (i + 3) % 3);
    }
}

// ---------------------------------------------------------------------------
// GEMM: 512 CTAs, one half-item each (HW work-conserving dispatch).
//   even bid: x-dist + fused softmax for c = bid>>1
//   odd  bid: cc-dist for c = bid>>1   (adjacent -> cc[c] shared in L2)
// ---------------------------------------------------------------------------
__global__ void __launch_bounds__(256, 2)
dist_gemm_all(float* __restrict__ out) {
    extern __shared__ char dsm[];
    uint32_t sb0 = smem_u32(dsm);
    uint32_t sbA = (sb0 + 1023u) & ~1023u;
    char* smA = dsm + (sbA - sb0);
    float* sCn = (float*)(smA + 3 * ST32);
    float* sXn = sCn + 128;

    const size_t OUT1 = (size_t)BD * C_DIM * CN;
    int t = threadIdx.x, lane = t & 31, w = t >> 5;
    int wm = (w & 3) * 32, wn = (w >> 2) * 64;

    int bid = blockIdx.x;
    int c = bid >> 1;
    int xpass = !(bid & 1);
    size_t boff = (size_t)c * 13312;                  // 128 rows * 104 uint4

    float acc[2][8][4];
    float* ebuf = (float*)smA;

    if (t < 128) sCn[t] = g_cn[(size_t)c * CN + t];
    else if (xpass) {
        int n = t - 128;
        float sv = 0.f;
        #pragma unroll
        for (int p = 0; p < NTILE; p++)
            sv += g_xn[(size_t)p * (C_DIM * BD) + (size_t)c * BD + n];
        sXn[n] = sv;
    }

    if (xpass) {
        // ---------------- x-distance + fused softmax ----------------
        gemm_pass<1>(sbA, g_ch + boff, g_cl + boff, g_xh + boff, g_xl + boff,
                     OF32_BH, acc, t, lane, wm, wn);

        #pragma unroll
        for (int mt = 0; mt < 2; mt++)
            #pragma unroll
            for (int np = 0; np < 8; np++)
                #pragma unroll
                for (int e = 0; e < 4; e++) {
                    int m = wm + mt * 16 + (lane >> 2) + ((e >> 1) << 3);
                    int n = wn + np * 8 + ((lane & 3) << 1) + (e & 1);
                    float d2 = sCn[m] + sXn[n] - 2.0f * acc[mt][np][e];
                    ebuf[n * 132 + m] = sqrtf(fmaxf(d2, 1e-12f));
                }
        __syncthreads();

        float* aout = out + OUT1;
        #pragma unroll
        for (int rj = 0; rj < 16; rj++) {
            int r = w * 16 + rj;                      // bd row
            float4 v = *(const float4*)&ebuf[r * 132 + lane * 4];
            *(float4*)(out + ((size_t)r * C_DIM + c) * CN + lane * 4) = v;
            float mn = fminf(fminf(v.x, v.y), fminf(v.z, v.w));
            #pragma unroll
            for (int o = 16; o > 0; o >>= 1)
                mn = fminf(mn, __shfl_xor_sync(0xffffffffu, mn, o));
            float e0 = __expf(-ALPHA * (v.x - mn));
            float e1 = __expf(-ALPHA * (v.y - mn));
            float e2 = __expf(-ALPHA * (v.z - mn));
            float e3 = __expf(-ALPHA * (v.w - mn));
            float sum = e0 + e1 + e2 + e3;
            #pragma unroll
            for (int o = 16; o > 0; o >>= 1)
                sum += __shfl_xor_sync(0xffffffffu, sum, o);
            float inv = 1.0f / sum;
            *(float4*)(aout + ((size_t)r * C_DIM + c) * CN + lane * 4) =
                make_float4(e0 * inv, e1 * inv, e2 * inv, e3 * inv);
        }
    } else {
        // ---------------- cc-distance ----------------
        gemm_pass<0>(sbA, g_ch + boff, g_cl + boff, g_ch + boff, g_cl + boff,
                     OF32_AH, acc, t, lane, wm, wn);

        #pragma unroll
        for (int mt = 0; mt < 2; mt++)
            #pragma unroll
            for (int np = 0; np < 8; np++)
                #pragma unroll
                for (int e = 0; e < 4; e++) {
                    int m = wm + mt * 16 + (lane >> 2) + ((e >> 1) << 3);
                    int n = wn + np * 8 + ((lane & 3) << 1) + (e & 1);
                    float d2 = sCn[m] + sCn[n] - 2.0f * acc[mt][np][e];
                    ebuf[n * 132 + m] = sqrtf(fmaxf(d2, 1e-12f));
                }
        __syncthreads();

        float* o2 = out + 2 * OUT1 + (size_t)c * (CN * CN);
        #pragma unroll
        for (int j = 0; j < 16; j++) {
            int idx = j * 256 + t;
            int n = idx >> 5, m4 = idx & 31;
            *(float4*)(o2 + (size_t)n * CN + m4 * 4) =
                *(const float4*)&ebuf[n * 132 + m4 * 4];
        }
    }
}

// ---------------------------------------------------------------------------
extern "C" void kernel_launch(void* const* d_in, const int* in_sizes, int n_in,
                              void* d_out, int out_size) {
    const float* x   = (const float*)d_in[0];
    const float* lnw = (const float*)d_in[1];
    const float* lnb = (const float*)d_in[2];
    const float* cc  = (const float*)d_in[3];
    float* out = (float*)d_out;

    const int SMEM = 3 * ST32 + 1024 + 1024;        // 100,352 B -> 2 CTAs/SM

    cudaFuncSetAttribute(dist_gemm_all, cudaFuncAttributeMaxDynamicSharedMemorySize, SMEM);

    prep_kernel<<<7424, 256>>>(x, lnw, lnb, cc);    // fused ln + cc split
    dist_gemm_all<<<2 * C_DIM, 256, SMEM>>>(out);
}